// round 6
// baseline (speedup 1.0000x reference)
#include <cuda_runtime.h>
#include <math.h>

#define Nn 1395
#define Ee 44640
#define GB 148          // persistent blocks (<= SM count, all co-resident)
#define NT 256
#define FC1_R 267840    // 1395 * 192
#define FC1_PER_BLK 1810  // ceil(267840/148)

// ---------------- scratch (device globals, allocation-free) ----------------
__device__ float g_deg [Nn];
__device__ float g_dinv[Nn];
__device__ __align__(16) float g_h0[Nn * 32];   // gcn1 transformed
__device__ __align__(16) float g_a1[Nn * 32];   // gcn1 neighbor aggregate
__device__ __align__(16) float g_t2[Nn * 30];   // gcn2 transformed
__device__ __align__(16) float g_a2[Nn * 30];   // gcn2 neighbor aggregate
__device__ __align__(16) float g_v [Nn * 192];  // QConv output, flattened
__device__ __align__(16) float g_p1[GB * 1024]; // fc1 partials
__device__ __align__(16) float g_v1[1024];
__device__ __align__(16) float g_p2[128 * 1024];// fc2 partials
__device__ __align__(16) float g_v2[1024];

// ---------------- software grid barrier ------------------------------------
__device__ int g_bar_count;          // zero-init; reset to 0 on every release
__device__ volatile int g_bar_gen;   // monotonically increasing generation

__device__ __forceinline__ void gridbar() {
    __threadfence();                 // publish this thread's writes
    __syncthreads();
    if (threadIdx.x == 0) {
        int gen = g_bar_gen;
        if (atomicAdd(&g_bar_count, 1) == GB - 1) {
            g_bar_count = 0;
            __threadfence();
            g_bar_gen = gen + 1;     // release
        } else {
            while (g_bar_gen == gen) { }   // volatile spin (L2)
        }
        __threadfence();
    }
    __syncthreads();
}

__device__ __forceinline__ float leaky(float v) { return v > 0.0f ? v : 0.2f * v; }

// ---------------- the whole network in one kernel ---------------------------
__global__ void __launch_bounds__(NT)
k_all(const float* __restrict__ x,   const int*   __restrict__ ei,
      const float* __restrict__ w1,  const float* __restrict__ b1,
      const float* __restrict__ w2,  const float* __restrict__ b2,
      const float* __restrict__ qw1, const float* __restrict__ qb1,
      const float* __restrict__ qw2, const float* __restrict__ qb2,
      const float* __restrict__ qw3, const float* __restrict__ qb3,
      const float* __restrict__ fw1, const float* __restrict__ fb1,
      const float* __restrict__ fw2, const float* __restrict__ fb2,
      const float* __restrict__ fw3, const float* __restrict__ fb3,
      float* __restrict__ out)
{
    const int tid = threadIdx.x;
    const int bid = blockIdx.x;
    const int gid = bid * NT + tid;
    const int gsz = GB * NT;            // 37888 threads

    // ---- P0: init deg=1 (self loop), zero aggregates ----
    for (int i = gid; i < Nn * 32; i += gsz) {
        if (i < Nn) g_deg[i] = 1.0f;
        g_a1[i] = 0.0f;
        if (i < Nn * 30) g_a2[i] = 0.0f;
    }
    gridbar();

    // ---- P1: degree count (atomics) + GCN1 transform (x[:, :3] == 0) ----
    for (int e = gid; e < Ee; e += gsz)
        atomicAdd(&g_deg[ei[Ee + e]], 1.0f);
    for (int i = gid; i < Nn * 32; i += gsz) {
        int n = i >> 5, c = i & 31;
        g_h0[i] = x[n * 6 + 3] * w1[3 * 32 + c]
                + x[n * 6 + 4] * w1[4 * 32 + c]
                + x[n * 6 + 5] * w1[5 * 32 + c];
    }
    gridbar();

    // ---- P2: dinv ----
    for (int i = gid; i < Nn; i += gsz)
        g_dinv[i] = rsqrtf(g_deg[i]);
    gridbar();

    // ---- P3: GCN1 neighbor aggregation (edge-parallel, lane=channel) ----
    #pragma unroll 4
    for (int i = gid; i < Ee * 32; i += gsz) {
        int e = i >> 5, c = i & 31;
        int s = ei[e], d = ei[Ee + e];
        float coef = g_dinv[s] * g_dinv[d];
        atomicAdd(&g_a1[d * 32 + c], coef * g_h0[s * 32 + c]);
    }
    gridbar();

    // ---- P4: GCN2 transform with GCN1 finalize (self-loop+bias+leaky) inline ----
    for (int i = gid; i < Nn * 30; i += gsz) {
        int n = i / 30, c = i % 30;
        float dii = g_dinv[n] * g_dinv[n];
        float acc = 0.0f;
        #pragma unroll
        for (int k = 0; k < 32; k++) {
            float h = leaky(g_a1[n * 32 + k] + dii * g_h0[n * 32 + k] + b1[k]);
            acc += h * __ldg(&w2[k * 30 + c]);
        }
        g_t2[i] = acc;
    }
    gridbar();

    // ---- P5: GCN2 neighbor aggregation ----
    #pragma unroll 4
    for (int i = gid; i < Ee * 32; i += gsz) {
        int e = i >> 5, c = i & 31;
        if (c < 30) {
            int s = ei[e], d = ei[Ee + e];
            float coef = g_dinv[s] * g_dinv[d];
            atomicAdd(&g_a2[d * 30 + c], coef * g_t2[s * 30 + c]);
        }
    }
    gridbar();

    // ---- P6: fused QConv chain 30->192->192->192 (GCN2 finalize inline) ----
    {
        __shared__ float s_in[5][30];
        __shared__ float sa[5][192];
        __shared__ float sb[5][192];
        const int c = tid;
        for (int grp = bid; grp < 279; grp += GB) {
            int nb = grp * 5;
            for (int i = tid; i < 5 * 30; i += NT) {
                int n = nb + i / 30, ch = i % 30;
                float di = g_dinv[n];
                float vv = g_a2[n * 30 + ch] + di * di * g_t2[n * 30 + ch] + b2[ch];
                s_in[i / 30][i % 30] = leaky(vv);
            }
            __syncthreads();
            if (c < 192) {
                float acc[5];
                #pragma unroll
                for (int g = 0; g < 5; g++) acc[g] = qb1[c];
                #pragma unroll
                for (int k = 0; k < 30; k++) {
                    float w = __ldg(&qw1[k * 192 + c]);
                    #pragma unroll
                    for (int g = 0; g < 5; g++) acc[g] += s_in[g][k] * w;
                }
                #pragma unroll
                for (int g = 0; g < 5; g++) sa[g][c] = acc[g];
            }
            __syncthreads();
            if (c < 192) {
                float acc[5];
                #pragma unroll
                for (int g = 0; g < 5; g++) acc[g] = qb2[c];
                #pragma unroll 8
                for (int k = 0; k < 192; k++) {
                    float w = __ldg(&qw2[k * 192 + c]);
                    #pragma unroll
                    for (int g = 0; g < 5; g++) acc[g] += sa[g][k] * w;
                }
                #pragma unroll
                for (int g = 0; g < 5; g++) sb[g][c] = acc[g];
            }
            __syncthreads();
            if (c < 192) {
                float acc[5];
                #pragma unroll
                for (int g = 0; g < 5; g++) acc[g] = qb3[c];
                #pragma unroll 8
                for (int k = 0; k < 192; k++) {
                    float w = __ldg(&qw3[k * 192 + c]);
                    #pragma unroll
                    for (int g = 0; g < 5; g++) acc[g] += sb[g][k] * w;
                }
                #pragma unroll
                for (int g = 0; g < 5; g++)
                    g_v[(nb + g) * 192 + c] = acc[g];
            }
            __syncthreads();
        }
    }
    gridbar();

    // ---- P7: fc1 partials — the HBM monster (stream 1.07 GB of fw1) ----
    {
        int lo = bid * FC1_PER_BLK;
        int hi = lo + FC1_PER_BLK; if (hi > FC1_R) hi = FC1_R;
        int j4 = tid * 4;
        const float4* W = (const float4*)(fw1 + (size_t)lo * 1024 + j4);
        float4 acc = make_float4(0.f, 0.f, 0.f, 0.f);
        #pragma unroll 4
        for (int r = lo; r < hi; r++) {
            float vv = __ldg(&g_v[r]);
            float4 w = __ldg(W);
            W += 256;                    // next row (1024 floats / 4)
            acc.x += vv * w.x; acc.y += vv * w.y;
            acc.z += vv * w.z; acc.w += vv * w.w;
        }
        *(float4*)(g_p1 + bid * 1024 + j4) = acc;
    }
    gridbar();

    // ---- P8: fc1 reduce + bias ----
    if (gid < 1024) {
        float s = 0.0f;
        #pragma unroll 4
        for (int b = 0; b < GB; b++) s += g_p1[b * 1024 + gid];
        g_v1[gid] = s + fb1[gid];
    }
    gridbar();

    // ---- P9: fc2 partials (128 blocks x 8 rows) ----
    if (bid < 128) {
        int r0 = bid * 8;
        int j4 = tid * 4;
        const float4* W = (const float4*)(fw2 + (size_t)r0 * 1024 + j4);
        float4 acc = make_float4(0.f, 0.f, 0.f, 0.f);
        #pragma unroll
        for (int r = 0; r < 8; r++) {
            float vv = g_v1[r0 + r];
            float4 w = __ldg(W);
            W += 256;
            acc.x += vv * w.x; acc.y += vv * w.y;
            acc.z += vv * w.z; acc.w += vv * w.w;
        }
        *(float4*)(g_p2 + bid * 1024 + j4) = acc;
    }
    gridbar();

    // ---- P10: fc2 reduce + bias ----
    if (gid < 1024) {
        float s = 0.0f;
        #pragma unroll 4
        for (int b = 0; b < 128; b++) s += g_p2[b * 1024 + gid];
        g_v2[gid] = s + fb2[gid];
    }
    gridbar();

    // ---- P11: fc3 (1024->64) + quaternion group-of-4 normalize (block 0) ----
    if (bid == 0) {
        __shared__ float s[4][64];
        __shared__ float s2[64];
        __shared__ float mag[16];
        int j = tid & 63, ch = tid >> 6;      // 4 row-chunks of 256
        float acc = 0.0f;
        int r0 = ch * 256;
        #pragma unroll 8
        for (int r = 0; r < 256; r++)
            acc += g_v2[r0 + r] * __ldg(&fw3[(r0 + r) * 64 + j]);
        s[ch][j] = acc;
        __syncthreads();
        if (tid < 64) s2[tid] = s[0][tid] + s[1][tid] + s[2][tid] + s[3][tid] + fb3[tid];
        __syncthreads();
        if (tid < 16) {
            float a = s2[4 * tid], b = s2[4 * tid + 1],
                  c = s2[4 * tid + 2], d = s2[4 * tid + 3];
            mag[tid] = sqrtf(a * a + b * b + c * c + d * d);
        }
        __syncthreads();
        if (tid < 64) out[tid] = s2[tid] / mag[tid >> 2];
    }
}

// ---------------- launcher: ONE kernel --------------------------------------
extern "C" void kernel_launch(void* const* d_in, const int* in_sizes, int n_in,
                              void* d_out, int out_size) {
    const float* x   = (const float*)d_in[0];
    const int*   ei  = (const int*)  d_in[1];
    const float* w1  = (const float*)d_in[2];
    const float* b1  = (const float*)d_in[3];
    const float* w2  = (const float*)d_in[4];
    const float* b2  = (const float*)d_in[5];
    const float* qw1 = (const float*)d_in[6];
    const float* qb1 = (const float*)d_in[7];
    const float* qw2 = (const float*)d_in[8];
    const float* qb2 = (const float*)d_in[9];
    const float* qw3 = (const float*)d_in[10];
    const float* qb3 = (const float*)d_in[11];
    const float* fw1 = (const float*)d_in[12];
    const float* fb1 = (const float*)d_in[13];
    const float* fw2 = (const float*)d_in[14];
    const float* fb2 = (const float*)d_in[15];
    const float* fw3 = (const float*)d_in[16];
    const float* fb3 = (const float*)d_in[17];

    k_all<<<GB, NT>>>(x, ei, w1, b1, w2, b2,
                      qw1, qb1, qw2, qb2, qw3, qb3,
                      fw1, fb1, fw2, fb2, fw3, fb3,
                      (float*)d_out);
}

// round 7
// speedup vs baseline: 1.4764x; 1.4764x over previous
#include <cuda_runtime.h>
#include <math.h>

#define Nn 1395
#define Ee 44640
#define GB 296          // persistent blocks: 2 per SM, all co-resident
#define NT 512
#define GSZ (GB * NT)   // 151552 threads
#define FC1_R 267840    // 1395 * 192
#define FC1_SUB (GB * 2)        // 592 sub-blocks of 256 threads
#define FC1_ROWS_PER_SUB 453    // ceil(267840 / 592)

// ---------------- scratch (device globals, allocation-free) ----------------
__device__ float g_deg [Nn];
__device__ float g_dinv[Nn];
__device__ __align__(16) float g_h0[Nn * 32];   // gcn1 transformed
__device__ __align__(16) float g_a1[Nn * 32];   // gcn1 neighbor aggregate
__device__ __align__(16) float g_t2[Nn * 30];   // gcn2 transformed
__device__ __align__(16) float g_a2[Nn * 30];   // gcn2 neighbor aggregate
__device__ __align__(16) float g_v [Nn * 192];  // QConv output, flattened
__device__ __align__(16) float g_p1[FC1_SUB * 1024];  // fc1 partials
__device__ __align__(16) float g_v1[1024];
__device__ __align__(16) float g_p2[256 * 1024];      // fc2 partials
__device__ __align__(16) float g_v2[1024];

// ---------------- software grid barrier ------------------------------------
__device__ int g_bar_count;          // zero-init; reset to 0 on every release
__device__ volatile int g_bar_gen;   // monotonically increasing generation

__device__ __forceinline__ void gridbar() {
    __threadfence();
    __syncthreads();
    if (threadIdx.x == 0) {
        int gen = g_bar_gen;
        if (atomicAdd(&g_bar_count, 1) == GB - 1) {
            g_bar_count = 0;
            __threadfence();
            g_bar_gen = gen + 1;     // release
        } else {
            while (g_bar_gen == gen) { }
        }
        __threadfence();
    }
    __syncthreads();
}

__device__ __forceinline__ float leaky(float v) { return v > 0.0f ? v : 0.2f * v; }

// ---------------- the whole network in one kernel ---------------------------
__global__ void __launch_bounds__(NT, 2)
k_all(const float* __restrict__ x,   const int*   __restrict__ ei,
      const float* __restrict__ w1,  const float* __restrict__ b1,
      const float* __restrict__ w2,  const float* __restrict__ b2,
      const float* __restrict__ qw1, const float* __restrict__ qb1,
      const float* __restrict__ qw2, const float* __restrict__ qb2,
      const float* __restrict__ qw3, const float* __restrict__ qb3,
      const float* __restrict__ fw1, const float* __restrict__ fb1,
      const float* __restrict__ fw2, const float* __restrict__ fb2,
      const float* __restrict__ fw3, const float* __restrict__ fb3,
      float* __restrict__ out)
{
    const int tid = threadIdx.x;
    const int bid = blockIdx.x;
    const int gid = bid * NT + tid;

    // ---- P0: init deg=1 (self loop), zero aggregates ----
    for (int i = gid; i < Nn * 32; i += GSZ) {
        if (i < Nn) g_deg[i] = 1.0f;
        g_a1[i] = 0.0f;
        if (i < Nn * 30) g_a2[i] = 0.0f;
    }
    gridbar();

    // ---- P1: degree count (atomics) + GCN1 transform (x[:, :3] == 0) ----
    for (int e = gid; e < Ee; e += GSZ)
        atomicAdd(&g_deg[ei[Ee + e]], 1.0f);
    for (int i = gid; i < Nn * 32; i += GSZ) {
        int n = i >> 5, c = i & 31;
        g_h0[i] = x[n * 6 + 3] * w1[3 * 32 + c]
                + x[n * 6 + 4] * w1[4 * 32 + c]
                + x[n * 6 + 5] * w1[5 * 32 + c];
    }
    gridbar();

    // ---- P2: dinv ----
    for (int i = gid; i < Nn; i += GSZ)
        g_dinv[i] = rsqrtf(g_deg[i]);
    gridbar();

    // ---- P3: GCN1 neighbor aggregation (edge-parallel, lane=channel) ----
    #pragma unroll 4
    for (int i = gid; i < Ee * 32; i += GSZ) {
        int e = i >> 5, c = i & 31;
        int s = ei[e], d = ei[Ee + e];
        float coef = g_dinv[s] * g_dinv[d];
        atomicAdd(&g_a1[d * 32 + c], coef * g_h0[s * 32 + c]);
    }
    gridbar();

    // ---- P4: GCN2 transform with GCN1 finalize inline ----
    for (int i = gid; i < Nn * 30; i += GSZ) {
        int n = i / 30, c = i % 30;
        float dii = g_dinv[n] * g_dinv[n];
        float acc = 0.0f;
        #pragma unroll
        for (int k = 0; k < 32; k++) {
            float h = leaky(g_a1[n * 32 + k] + dii * g_h0[n * 32 + k] + b1[k]);
            acc += h * __ldg(&w2[k * 30 + c]);
        }
        g_t2[i] = acc;
    }
    gridbar();

    // ---- P5: GCN2 neighbor aggregation ----
    #pragma unroll 4
    for (int i = gid; i < Ee * 32; i += GSZ) {
        int e = i >> 5, c = i & 31;
        if (c < 30) {
            int s = ei[e], d = ei[Ee + e];
            float coef = g_dinv[s] * g_dinv[d];
            atomicAdd(&g_a2[d * 30 + c], coef * g_t2[s * 30 + c]);
        }
    }
    gridbar();

    // ---- P6: fused QConv chain 30->192->192->192 (GCN2 finalize inline) ----
    // 296 blocks x 5 nodes = 1480 >= 1395 (single pass); threads 0..191 active.
    {
        __shared__ float s_in[5][30];
        __shared__ float sa[5][192];
        __shared__ float sb[5][192];
        const int c = tid;
        int nb = bid * 5;
        if (nb < Nn) {
            int nodes = (Nn - nb < 5) ? (Nn - nb) : 5;
            for (int i = tid; i < nodes * 30; i += NT) {
                int n = nb + i / 30, ch = i % 30;
                float di = g_dinv[n];
                float vv = g_a2[n * 30 + ch] + di * di * g_t2[n * 30 + ch] + b2[ch];
                s_in[i / 30][i % 30] = leaky(vv);
            }
            __syncthreads();
            if (c < 192) {
                float acc[5];
                #pragma unroll
                for (int g = 0; g < 5; g++) acc[g] = qb1[c];
                #pragma unroll
                for (int k = 0; k < 30; k++) {
                    float w = __ldg(&qw1[k * 192 + c]);
                    #pragma unroll
                    for (int g = 0; g < 5; g++) acc[g] += s_in[g][k] * w;
                }
                #pragma unroll
                for (int g = 0; g < 5; g++) sa[g][c] = acc[g];
            }
            __syncthreads();
            if (c < 192) {
                float acc[5];
                #pragma unroll
                for (int g = 0; g < 5; g++) acc[g] = qb2[c];
                #pragma unroll 8
                for (int k = 0; k < 192; k++) {
                    float w = __ldg(&qw2[k * 192 + c]);
                    #pragma unroll
                    for (int g = 0; g < 5; g++) acc[g] += sa[g][k] * w;
                }
                #pragma unroll
                for (int g = 0; g < 5; g++) sb[g][c] = acc[g];
            }
            __syncthreads();
            if (c < 192) {
                float acc[5];
                #pragma unroll
                for (int g = 0; g < 5; g++) acc[g] = qb3[c];
                #pragma unroll 8
                for (int k = 0; k < 192; k++) {
                    float w = __ldg(&qw3[k * 192 + c]);
                    #pragma unroll
                    for (int g = 0; g < 5; g++) acc[g] += sb[g][k] * w;
                }
                #pragma unroll
                for (int g = 0; g < 5; g++)
                    if (g < nodes) g_v[(nb + g) * 192 + c] = acc[g];
            }
        }
    }
    gridbar();

    // ---- P7: fc1 partials — stream 1.07 GB of fw1 at full MLP ----
    // 592 sub-blocks of 256 threads; each streams 453 contiguous rows.
    {
        int sub = bid * 2 + (tid >> 8);          // 0..591
        int lt  = tid & 255;                     // lane within sub-block
        int lo  = sub * FC1_ROWS_PER_SUB;
        int hi  = lo + FC1_ROWS_PER_SUB; if (hi > FC1_R) hi = FC1_R;
        int j4  = lt * 4;
        const float4* W = (const float4*)(fw1 + (size_t)lo * 1024 + j4);
        float4 acc = make_float4(0.f, 0.f, 0.f, 0.f);
        #pragma unroll 8
        for (int r = lo; r < hi; r++) {
            float vv = __ldg(&g_v[r]);
            float4 w = __ldcs(W);                // streaming: no reuse
            W += 256;                            // next row
            acc.x += vv * w.x; acc.y += vv * w.y;
            acc.z += vv * w.z; acc.w += vv * w.w;
        }
        *(float4*)(g_p1 + (size_t)sub * 1024 + j4) = acc;
    }
    gridbar();

    // ---- P8: fc1 reduce + bias ----
    if (gid < 1024) {
        float s = 0.0f;
        #pragma unroll 4
        for (int b = 0; b < FC1_SUB; b++) s += g_p1[b * 1024 + gid];
        g_v1[gid] = s + fb1[gid];
    }
    gridbar();

    // ---- P9: fc2 partials: 256 sub-blocks x 4 rows ----
    if (bid < 128) {
        int sub = bid * 2 + (tid >> 8);          // 0..255
        int lt  = tid & 255;
        int r0  = sub * 4;
        int j4  = lt * 4;
        const float4* W = (const float4*)(fw2 + (size_t)r0 * 1024 + j4);
        float4 acc = make_float4(0.f, 0.f, 0.f, 0.f);
        #pragma unroll
        for (int r = 0; r < 4; r++) {
            float vv = g_v1[r0 + r];
            float4 w = __ldg(W);
            W += 256;
            acc.x += vv * w.x; acc.y += vv * w.y;
            acc.z += vv * w.z; acc.w += vv * w.w;
        }
        *(float4*)(g_p2 + (size_t)sub * 1024 + j4) = acc;
    }
    gridbar();

    // ---- P10: fc2 reduce + bias ----
    if (gid < 1024) {
        float s = 0.0f;
        #pragma unroll 4
        for (int b = 0; b < 256; b++) s += g_p2[b * 1024 + gid];
        g_v2[gid] = s + fb2[gid];
    }
    gridbar();

    // ---- P11: fc3 (1024->64) + quaternion group-of-4 normalize (block 0) ----
    if (bid == 0 && tid < 256) {
        __shared__ float s[4][64];
        __shared__ float s2[64];
        __shared__ float mag[16];
        int j = tid & 63, ch = tid >> 6;
        float acc = 0.0f;
        int r0 = ch * 256;
        #pragma unroll 8
        for (int r = 0; r < 256; r++)
            acc += g_v2[r0 + r] * __ldg(&fw3[(r0 + r) * 64 + j]);
        s[ch][j] = acc;
        __syncwarp();
        asm volatile("bar.sync 1, 256;" ::: "memory");
        if (tid < 64) s2[tid] = s[0][tid] + s[1][tid] + s[2][tid] + s[3][tid] + fb3[tid];
        asm volatile("bar.sync 1, 256;" ::: "memory");
        if (tid < 16) {
            float a = s2[4 * tid], b = s2[4 * tid + 1],
                  c = s2[4 * tid + 2], d = s2[4 * tid + 3];
            mag[tid] = sqrtf(a * a + b * b + c * c + d * d);
        }
        asm volatile("bar.sync 1, 256;" ::: "memory");
        if (tid < 64) out[tid] = s2[tid] / mag[tid >> 2];
    }
}

// ---------------- launcher: ONE kernel --------------------------------------
extern "C" void kernel_launch(void* const* d_in, const int* in_sizes, int n_in,
                              void* d_out, int out_size) {
    const float* x   = (const float*)d_in[0];
    const int*   ei  = (const int*)  d_in[1];
    const float* w1  = (const float*)d_in[2];
    const float* b1  = (const float*)d_in[3];
    const float* w2  = (const float*)d_in[4];
    const float* b2  = (const float*)d_in[5];
    const float* qw1 = (const float*)d_in[6];
    const float* qb1 = (const float*)d_in[7];
    const float* qw2 = (const float*)d_in[8];
    const float* qb2 = (const float*)d_in[9];
    const float* qw3 = (const float*)d_in[10];
    const float* qb3 = (const float*)d_in[11];
    const float* fw1 = (const float*)d_in[12];
    const float* fb1 = (const float*)d_in[13];
    const float* fw2 = (const float*)d_in[14];
    const float* fb2 = (const float*)d_in[15];
    const float* fw3 = (const float*)d_in[16];
    const float* fb3 = (const float*)d_in[17];

    k_all<<<GB, NT>>>(x, ei, w1, b1, w2, b2,
                      qw1, qb1, qw2, qb2, qw3, qb3,
                      fw1, fb1, fw2, fb2, fw3, fb3,
                      (float*)d_out);
}

// round 8
// speedup vs baseline: 1.8812x; 1.2742x over previous
#include <cuda_runtime.h>
#include <math.h>

#define Nn 1395
#define Ee 44640
#define GB_PRE 296      // persistent blocks for k_pre: 2/SM
#define NT 512
#define GSZ (GB_PRE * NT)
#define FC1_R 267840    // 1395 * 192
#define FC1_GRID 1184   // 148 SMs * 8 blocks, single wave at 100% occ
#define GB_POST 64

// ---------------- scratch (device globals, allocation-free) ----------------
__device__ float g_deg [Nn];
__device__ float g_dinv[Nn];
__device__ __align__(16) float g_h0[Nn * 32];
__device__ __align__(16) float g_a1[Nn * 32];
__device__ __align__(16) float g_t2[Nn * 30];
__device__ __align__(16) float g_a2[Nn * 30];
__device__ __align__(16) float g_v [Nn * 192];
__device__ __align__(16) float g_p1[FC1_GRID * 1024];   // fc1 partials (4.85 MB)
__device__ __align__(16) float g_v1[1024];
__device__ __align__(16) float g_p2[GB_POST * 1024];    // fc2 partials
__device__ __align__(16) float g_v2[1024];

// ---------------- software grid barrier (shared, count resets each use) ----
__device__ int g_bar_count;
__device__ volatile int g_bar_gen;

__device__ __forceinline__ void gridbar(int nblocks) {
    __threadfence();
    __syncthreads();
    if (threadIdx.x == 0) {
        int gen = g_bar_gen;
        if (atomicAdd(&g_bar_count, 1) == nblocks - 1) {
            g_bar_count = 0;
            __threadfence();
            g_bar_gen = gen + 1;
        } else {
            while (g_bar_gen == gen) { }
        }
        __threadfence();
    }
    __syncthreads();
}

__device__ __forceinline__ float leaky(float v) { return v > 0.0f ? v : 0.2f * v; }

// ============================================================================
// Kernel 1: graph preprocessing + GCN1 + GCN2 + fused QConv chain -> g_v
// ============================================================================
__global__ void __launch_bounds__(NT, 2)
k_pre(const float* __restrict__ x,   const int*   __restrict__ ei,
      const float* __restrict__ w1,  const float* __restrict__ b1,
      const float* __restrict__ w2,  const float* __restrict__ b2,
      const float* __restrict__ qw1, const float* __restrict__ qb1,
      const float* __restrict__ qw2, const float* __restrict__ qb2,
      const float* __restrict__ qw3, const float* __restrict__ qb3)
{
    const int tid = threadIdx.x;
    const int bid = blockIdx.x;
    const int gid = bid * NT + tid;

    // ---- P0: init deg=1 (self loop), zero aggregates ----
    for (int i = gid; i < Nn * 32; i += GSZ) {
        if (i < Nn) g_deg[i] = 1.0f;
        g_a1[i] = 0.0f;
        if (i < Nn * 30) g_a2[i] = 0.0f;
    }
    gridbar(GB_PRE);

    // ---- P1: degree count + GCN1 transform (x[:, :3] == 0) ----
    for (int e = gid; e < Ee; e += GSZ)
        atomicAdd(&g_deg[ei[Ee + e]], 1.0f);
    for (int i = gid; i < Nn * 32; i += GSZ) {
        int n = i >> 5, c = i & 31;
        g_h0[i] = x[n * 6 + 3] * w1[3 * 32 + c]
                + x[n * 6 + 4] * w1[4 * 32 + c]
                + x[n * 6 + 5] * w1[5 * 32 + c];
    }
    gridbar(GB_PRE);

    // ---- P2: dinv ----
    for (int i = gid; i < Nn; i += GSZ)
        g_dinv[i] = rsqrtf(g_deg[i]);
    gridbar(GB_PRE);

    // ---- P3: GCN1 neighbor aggregation ----
    #pragma unroll 4
    for (int i = gid; i < Ee * 32; i += GSZ) {
        int e = i >> 5, c = i & 31;
        int s = ei[e], d = ei[Ee + e];
        float coef = g_dinv[s] * g_dinv[d];
        atomicAdd(&g_a1[d * 32 + c], coef * g_h0[s * 32 + c]);
    }
    gridbar(GB_PRE);

    // ---- P4: GCN2 transform with GCN1 finalize inline ----
    for (int i = gid; i < Nn * 30; i += GSZ) {
        int n = i / 30, c = i % 30;
        float dii = g_dinv[n] * g_dinv[n];
        float acc = 0.0f;
        #pragma unroll
        for (int k = 0; k < 32; k++) {
            float h = leaky(g_a1[n * 32 + k] + dii * g_h0[n * 32 + k] + b1[k]);
            acc += h * __ldg(&w2[k * 30 + c]);
        }
        g_t2[i] = acc;
    }
    gridbar(GB_PRE);

    // ---- P5: GCN2 neighbor aggregation ----
    #pragma unroll 4
    for (int i = gid; i < Ee * 32; i += GSZ) {
        int e = i >> 5, c = i & 31;
        if (c < 30) {
            int s = ei[e], d = ei[Ee + e];
            float coef = g_dinv[s] * g_dinv[d];
            atomicAdd(&g_a2[d * 30 + c], coef * g_t2[s * 30 + c]);
        }
    }
    gridbar(GB_PRE);

    // ---- P6: fused QConv 30->192->192->192 (GCN2 finalize inline) ----
    {
        __shared__ float s_in[5][30];
        __shared__ float sa[5][192];
        __shared__ float sb[5][192];
        const int c = tid;
        int nb = bid * 5;
        if (nb < Nn) {
            int nodes = (Nn - nb < 5) ? (Nn - nb) : 5;
            for (int i = tid; i < nodes * 30; i += NT) {
                int n = nb + i / 30, ch = i % 30;
                float di = g_dinv[n];
                float vv = g_a2[n * 30 + ch] + di * di * g_t2[n * 30 + ch] + b2[ch];
                s_in[i / 30][i % 30] = leaky(vv);
            }
            __syncthreads();
            if (c < 192) {
                float acc[5];
                #pragma unroll
                for (int g = 0; g < 5; g++) acc[g] = qb1[c];
                #pragma unroll
                for (int k = 0; k < 30; k++) {
                    float w = __ldg(&qw1[k * 192 + c]);
                    #pragma unroll
                    for (int g = 0; g < 5; g++) acc[g] += s_in[g][k] * w;
                }
                #pragma unroll
                for (int g = 0; g < 5; g++) sa[g][c] = acc[g];
            }
            __syncthreads();
            if (c < 192) {
                float acc[5];
                #pragma unroll
                for (int g = 0; g < 5; g++) acc[g] = qb2[c];
                #pragma unroll 8
                for (int k = 0; k < 192; k++) {
                    float w = __ldg(&qw2[k * 192 + c]);
                    #pragma unroll
                    for (int g = 0; g < 5; g++) acc[g] += sa[g][k] * w;
                }
                #pragma unroll
                for (int g = 0; g < 5; g++) sb[g][c] = acc[g];
            }
            __syncthreads();
            if (c < 192) {
                float acc[5];
                #pragma unroll
                for (int g = 0; g < 5; g++) acc[g] = qb3[c];
                #pragma unroll 8
                for (int k = 0; k < 192; k++) {
                    float w = __ldg(&qw3[k * 192 + c]);
                    #pragma unroll
                    for (int g = 0; g < 5; g++) acc[g] += sb[g][k] * w;
                }
                #pragma unroll
                for (int g = 0; g < 5; g++)
                    if (g < nodes) g_v[(nb + g) * 192 + c] = acc[g];
            }
        }
    }
}

// ============================================================================
// Kernel 2: fc1 partials — lean streaming kernel, 100% occupancy, 1 wave.
// Row r handled by block (r % 1184); block-wide float4 read = one 4KB burst.
// ============================================================================
__global__ void __launch_bounds__(256, 8)
k_fc1(const float* __restrict__ fw1)
{
    const float4* W = (const float4*)fw1 + (size_t)blockIdx.x * 256 + threadIdx.x;
    const float*  V = g_v + blockIdx.x;
    const int n = (FC1_R - blockIdx.x + FC1_GRID - 1) / FC1_GRID;  // 226 or 227
    float4 acc = make_float4(0.f, 0.f, 0.f, 0.f);
    #pragma unroll 4
    for (int it = 0; it < n; it++) {
        float  vv = __ldg(V);
        float4 w  = __ldcs(W);
        V += FC1_GRID;
        W += (size_t)FC1_GRID * 256;
        acc.x += vv * w.x; acc.y += vv * w.y;
        acc.z += vv * w.z; acc.w += vv * w.w;
    }
    ((float4*)(g_p1 + (size_t)blockIdx.x * 1024))[threadIdx.x] = acc;
}

// ============================================================================
// Kernel 3: fc1 reduce -> fc2 -> fc2 reduce -> fc3 + quaternion normalize
// Persistent 64 blocks x 512 threads with grid barriers.
// ============================================================================
__global__ void __launch_bounds__(NT, 2)
k_post(const float* __restrict__ fb1,
       const float* __restrict__ fw2, const float* __restrict__ fb2,
       const float* __restrict__ fw3, const float* __restrict__ fb3,
       float* __restrict__ out)
{
    const int tid = threadIdx.x;
    const int bid = blockIdx.x;
    const int wid  = tid >> 5;
    const int lane = tid & 31;

    // ---- A: v1[j] = sum_b p1[b][j] + fb1[j]; warp-per-output (1024 warps) --
    {
        int j = bid * 16 + wid;              // 64 blocks * 16 warps = 1024
        float s = 0.0f;
        #pragma unroll 4
        for (int b = lane; b < FC1_GRID; b += 32)
            s += g_p1[(size_t)b * 1024 + j];
        #pragma unroll
        for (int o = 16; o > 0; o >>= 1)
            s += __shfl_down_sync(0xffffffffu, s, o);
        if (lane == 0) g_v1[j] = s + fb1[j];
    }
    gridbar(GB_POST);

    // ---- B: fc2 partials: block b covers rows [b*16, b*16+16) ----
    {
        __shared__ float4 sh[256];
        int half = tid >> 8, lt = tid & 255;
        int r0 = bid * 16 + half * 8;
        const float4* W = (const float4*)fw2 + (size_t)r0 * 256 + lt;
        float4 acc = make_float4(0.f, 0.f, 0.f, 0.f);
        #pragma unroll
        for (int r = 0; r < 8; r++) {
            float vv = g_v1[r0 + r];
            float4 w = __ldg(W);
            W += 256;
            acc.x += vv * w.x; acc.y += vv * w.y;
            acc.z += vv * w.z; acc.w += vv * w.w;
        }
        if (half == 1) sh[lt] = acc;
        __syncthreads();
        if (half == 0) {
            float4 o = sh[lt];
            acc.x += o.x; acc.y += o.y; acc.z += o.z; acc.w += o.w;
            ((float4*)(g_p2 + (size_t)bid * 1024))[lt] = acc;
        }
    }
    gridbar(GB_POST);

    // ---- C: v2[j] = sum_b p2[b][j] + fb2[j]; warp-per-output ----
    {
        int j = bid * 16 + wid;
        float s = g_p2[(size_t)lane * 1024 + j]
                + g_p2[(size_t)(lane + 32) * 1024 + j];
        #pragma unroll
        for (int o = 16; o > 0; o >>= 1)
            s += __shfl_down_sync(0xffffffffu, s, o);
        if (lane == 0) g_v2[j] = s + fb2[j];
    }
    gridbar(GB_POST);

    // ---- D: fc3 (1024->64) + quaternion group-of-4 normalize (block 0) ----
    if (bid == 0 && tid < 256) {
        __shared__ float s[4][64];
        __shared__ float s2[64];
        __shared__ float mag[16];
        int j = tid & 63, ch = tid >> 6;
        float acc = 0.0f;
        int r0 = ch * 256;
        #pragma unroll 8
        for (int r = 0; r < 256; r++)
            acc += g_v2[r0 + r] * __ldg(&fw3[(r0 + r) * 64 + j]);
        s[ch][j] = acc;
        asm volatile("bar.sync 1, 256;" ::: "memory");
        if (tid < 64) s2[tid] = s[0][tid] + s[1][tid] + s[2][tid] + s[3][tid] + fb3[tid];
        asm volatile("bar.sync 1, 256;" ::: "memory");
        if (tid < 16) {
            float a = s2[4 * tid], b = s2[4 * tid + 1],
                  c = s2[4 * tid + 2], d = s2[4 * tid + 3];
            mag[tid] = sqrtf(a * a + b * b + c * c + d * d);
        }
        asm volatile("bar.sync 1, 256;" ::: "memory");
        if (tid < 64) out[tid] = s2[tid] / mag[tid >> 2];
    }
}

// ---------------- launcher: three kernels -----------------------------------
extern "C" void kernel_launch(void* const* d_in, const int* in_sizes, int n_in,
                              void* d_out, int out_size) {
    const float* x   = (const float*)d_in[0];
    const int*   ei  = (const int*)  d_in[1];
    const float* w1  = (const float*)d_in[2];
    const float* b1  = (const float*)d_in[3];
    const float* w2  = (const float*)d_in[4];
    const float* b2  = (const float*)d_in[5];
    const float* qw1 = (const float*)d_in[6];
    const float* qb1 = (const float*)d_in[7];
    const float* qw2 = (const float*)d_in[8];
    const float* qb2 = (const float*)d_in[9];
    const float* qw3 = (const float*)d_in[10];
    const float* qb3 = (const float*)d_in[11];
    const float* fw1 = (const float*)d_in[12];
    const float* fb1 = (const float*)d_in[13];
    const float* fw2 = (const float*)d_in[14];
    const float* fb2 = (const float*)d_in[15];
    const float* fw3 = (const float*)d_in[16];
    const float* fb3 = (const float*)d_in[17];

    k_pre <<<GB_PRE, NT>>>(x, ei, w1, b1, w2, b2,
                           qw1, qb1, qw2, qb2, qw3, qb3);
    k_fc1 <<<FC1_GRID, 256>>>(fw1);
    k_post<<<GB_POST, NT>>>(fb1, fw2, fb2, fw3, fb3, (float*)d_out);
}

// round 9
// speedup vs baseline: 1.8879x; 1.0035x over previous
#include <cuda_runtime.h>
#include <math.h>

#define Nn 1395
#define Ee 44640
#define MAXDEG 96        // >> max in-degree (Binomial mean 32, ~11 sigma headroom)
#define GB_PRE 140       // k_pre blocks (10 QConv nodes each; 140*10 >= 1395)
#define NTP 384
#define GSZP (GB_PRE * NTP)      // 53760 threads, 1680 warps
#define FC1_R 267840     // 1395 * 192
#define FC1_GRID 1184    // 148 SMs * 8 blocks, one wave at 100% occ
#define GB_POST 64
#define NT 512

// ---------------- scratch (device globals, allocation-free) ----------------
__device__ int   g_cnt[Nn];                 // in-degree (excl. self loop)
__device__ int   g_csc[Nn * MAXDEG];        // src lists per destination
__device__ __align__(16) float g_h0[Nn * 32];   // gcn1 transformed
__device__ __align__(16) float g_t2[Nn * 30];   // gcn2 transformed (pre-agg)
__device__ __align__(16) float g_h2[Nn * 30];   // gcn2 output (post leaky)
__device__ __align__(16) float g_v [Nn * 192];  // QConv output, flattened
__device__ __align__(16) float g_p1[FC1_GRID * 1024];
__device__ __align__(16) float g_v1[1024];
__device__ __align__(16) float g_p2[GB_POST * 1024];
__device__ __align__(16) float g_v2[1024];

// ---------------- software grid barrier ------------------------------------
__device__ int g_bar_count;
__device__ volatile int g_bar_gen;

__device__ __forceinline__ void gridbar(int nblocks) {
    __threadfence();
    __syncthreads();
    if (threadIdx.x == 0) {
        int gen = g_bar_gen;
        if (atomicAdd(&g_bar_count, 1) == nblocks - 1) {
            g_bar_count = 0;
            __threadfence();
            g_bar_gen = gen + 1;
        } else {
            while (g_bar_gen == gen) { }
        }
        __threadfence();
    }
    __syncthreads();
}

__device__ __forceinline__ float leaky(float v) { return v > 0.0f ? v : 0.2f * v; }

// ============================================================================
// Kernel 1: CSC build + GCN1 + GCN2 (gather) + fused QConv chain -> g_v
// ============================================================================
__global__ void __launch_bounds__(NTP)
k_pre(const float* __restrict__ x,   const int*   __restrict__ ei,
      const float* __restrict__ w1,  const float* __restrict__ b1,
      const float* __restrict__ w2,  const float* __restrict__ b2,
      const float* __restrict__ qw1, const float* __restrict__ qb1,
      const float* __restrict__ qw2, const float* __restrict__ qb2,
      const float* __restrict__ qw3, const float* __restrict__ qb3)
{
    const int tid  = threadIdx.x;
    const int bid  = blockIdx.x;
    const int gid  = bid * NTP + tid;
    const int wgid = gid >> 5;
    const int lane = gid & 31;

    // ---- P0: zero edge counters ----
    for (int i = gid; i < Nn; i += GSZP) g_cnt[i] = 0;
    gridbar(GB_PRE);

    // ---- P1: CSC fill (44640 atomics) + GCN1 transform (x[:, :3] == 0) ----
    for (int e = gid; e < Ee; e += GSZP) {
        int s = ei[e], d = ei[Ee + e];
        int pos = atomicAdd(&g_cnt[d], 1);
        if (pos < MAXDEG) g_csc[d * MAXDEG + pos] = s;
    }
    for (int i = gid; i < Nn * 32; i += GSZP) {
        int n = i >> 5, c = i & 31;
        g_h0[i] = x[n * 6 + 3] * w1[3 * 32 + c]
                + x[n * 6 + 4] * w1[4 * 32 + c]
                + x[n * 6 + 5] * w1[5 * 32 + c];
    }
    gridbar(GB_PRE);

    // ---- P2: GCN1 gather-aggregate + finalize + GCN2 transform (fused) ----
    // Warp per destination node; lane = channel (32).
    for (int d = wgid; d < Nn; d += GSZP / 32) {
        int cntd = g_cnt[d];
        float dinvd = rsqrtf((float)(cntd + 1));
        float acc = dinvd * dinvd * g_h0[d * 32 + lane];   // self loop
        const int* lst = g_csc + d * MAXDEG;
        #pragma unroll 4
        for (int j = 0; j < cntd; j++) {
            int s = lst[j];                                 // warp-uniform
            float coef = rsqrtf((float)(g_cnt[s] + 1)) * dinvd;
            acc += coef * g_h0[s * 32 + lane];
        }
        float h1 = leaky(acc + b1[lane]);
        // GCN2 transform: t2[d,c] = sum_k h1_k * w2[k,c]  (c = lane < 30)
        float t = 0.0f;
        #pragma unroll
        for (int k = 0; k < 32; k++) {
            float hk = __shfl_sync(0xffffffffu, h1, k);
            if (lane < 30) t += hk * __ldg(&w2[k * 30 + lane]);
        }
        if (lane < 30) g_t2[d * 30 + lane] = t;
    }
    gridbar(GB_PRE);

    // ---- P3: GCN2 gather-aggregate + finalize ----
    for (int d = wgid; d < Nn; d += GSZP / 32) {
        int cntd = g_cnt[d];
        float dinvd = rsqrtf((float)(cntd + 1));
        float acc = (lane < 30) ? dinvd * dinvd * g_t2[d * 30 + lane] : 0.0f;
        const int* lst = g_csc + d * MAXDEG;
        #pragma unroll 4
        for (int j = 0; j < cntd; j++) {
            int s = lst[j];
            float coef = rsqrtf((float)(g_cnt[s] + 1)) * dinvd;
            if (lane < 30) acc += coef * g_t2[s * 30 + lane];
        }
        if (lane < 30) g_h2[d * 30 + lane] = leaky(acc + b2[lane]);
    }
    gridbar(GB_PRE);

    // ---- P4: fused QConv chain 30->192->192->192, 10 nodes per block ----
    {
        __shared__ float s_in[10][30];
        __shared__ float sa[10][192];
        __shared__ float sb[10][192];
        const int half = tid / 192;          // 0 or 1
        const int c    = tid - half * 192;   // 0..191
        const int nb   = bid * 10;

        for (int i = tid; i < 10 * 30; i += NTP) {
            int node = nb + i / 30;
            if (node < Nn) s_in[i / 30][i % 30] = g_h2[node * 30 + (i % 30)];
        }
        __syncthreads();

        float acc[5];
        #pragma unroll
        for (int g = 0; g < 5; g++) acc[g] = qb1[c];
        #pragma unroll
        for (int k = 0; k < 30; k++) {
            float w = __ldg(&qw1[k * 192 + c]);
            #pragma unroll
            for (int g = 0; g < 5; g++) acc[g] += s_in[half * 5 + g][k] * w;
        }
        #pragma unroll
        for (int g = 0; g < 5; g++) sa[half * 5 + g][c] = acc[g];
        __syncthreads();

        #pragma unroll
        for (int g = 0; g < 5; g++) acc[g] = qb2[c];
        #pragma unroll 8
        for (int k = 0; k < 192; k++) {
            float w = __ldg(&qw2[k * 192 + c]);
            #pragma unroll
            for (int g = 0; g < 5; g++) acc[g] += sa[half * 5 + g][k] * w;
        }
        #pragma unroll
        for (int g = 0; g < 5; g++) sb[half * 5 + g][c] = acc[g];
        __syncthreads();

        #pragma unroll
        for (int g = 0; g < 5; g++) acc[g] = qb3[c];
        #pragma unroll 8
        for (int k = 0; k < 192; k++) {
            float w = __ldg(&qw3[k * 192 + c]);
            #pragma unroll
            for (int g = 0; g < 5; g++) acc[g] += sb[half * 5 + g][k] * w;
        }
        #pragma unroll
        for (int g = 0; g < 5; g++) {
            int node = nb + half * 5 + g;
            if (node < Nn) g_v[node * 192 + c] = acc[g];
        }
    }
}

// ============================================================================
// Kernel 2: fc1 partials — lean streaming kernel, 100% occupancy, one wave.
// ============================================================================
__global__ void __launch_bounds__(256, 8)
k_fc1(const float* __restrict__ fw1)
{
    const float4* W = (const float4*)fw1 + (size_t)blockIdx.x * 256 + threadIdx.x;
    const float*  V = g_v + blockIdx.x;
    const int n = (FC1_R - blockIdx.x + FC1_GRID - 1) / FC1_GRID;
    float4 acc = make_float4(0.f, 0.f, 0.f, 0.f);
    #pragma unroll 4
    for (int it = 0; it < n; it++) {
        float  vv = __ldg(V);
        float4 w  = __ldcs(W);
        V += FC1_GRID;
        W += (size_t)FC1_GRID * 256;
        acc.x += vv * w.x; acc.y += vv * w.y;
        acc.z += vv * w.z; acc.w += vv * w.w;
    }
    ((float4*)(g_p1 + (size_t)blockIdx.x * 1024))[threadIdx.x] = acc;
}

// ============================================================================
// Kernel 3: fc1 reduce -> fc2 -> fc2 reduce -> fc3 + quaternion normalize
// ============================================================================
__global__ void __launch_bounds__(NT, 2)
k_post(const float* __restrict__ fb1,
       const float* __restrict__ fw2, const float* __restrict__ fb2,
       const float* __restrict__ fw3, const float* __restrict__ fb3,
       float* __restrict__ out)
{
    const int tid = threadIdx.x;
    const int bid = blockIdx.x;
    const int wid  = tid >> 5;
    const int lane = tid & 31;

    // ---- A: v1[j] = sum_b p1[b][j] + fb1[j]; warp-per-output ----
    {
        int j = bid * 16 + wid;
        float s = 0.0f;
        #pragma unroll 4
        for (int b = lane; b < FC1_GRID; b += 32)
            s += g_p1[(size_t)b * 1024 + j];
        #pragma unroll
        for (int o = 16; o > 0; o >>= 1)
            s += __shfl_down_sync(0xffffffffu, s, o);
        if (lane == 0) g_v1[j] = s + fb1[j];
    }
    gridbar(GB_POST);

    // ---- B: fc2 partials: block b covers rows [b*16, b*16+16) ----
    {
        __shared__ float4 sh[256];
        int half = tid >> 8, lt = tid & 255;
        int r0 = bid * 16 + half * 8;
        const float4* W = (const float4*)fw2 + (size_t)r0 * 256 + lt;
        float4 acc = make_float4(0.f, 0.f, 0.f, 0.f);
        #pragma unroll
        for (int r = 0; r < 8; r++) {
            float vv = g_v1[r0 + r];
            float4 w = __ldg(W);
            W += 256;
            acc.x += vv * w.x; acc.y += vv * w.y;
            acc.z += vv * w.z; acc.w += vv * w.w;
        }
        if (half == 1) sh[lt] = acc;
        __syncthreads();
        if (half == 0) {
            float4 o = sh[lt];
            acc.x += o.x; acc.y += o.y; acc.z += o.z; acc.w += o.w;
            ((float4*)(g_p2 + (size_t)bid * 1024))[lt] = acc;
        }
    }
    gridbar(GB_POST);

    // ---- C: v2[j] = sum_b p2[b][j] + fb2[j]; warp-per-output ----
    {
        int j = bid * 16 + wid;
        float s = g_p2[(size_t)lane * 1024 + j]
                + g_p2[(size_t)(lane + 32) * 1024 + j];
        #pragma unroll
        for (int o = 16; o > 0; o >>= 1)
            s += __shfl_down_sync(0xffffffffu, s, o);
        if (lane == 0) g_v2[j] = s + fb2[j];
    }
    gridbar(GB_POST);

    // ---- D: fc3 (1024->64) + quaternion group-of-4 normalize (block 0) ----
    if (bid == 0 && tid < 256) {
        __shared__ float s[4][64];
        __shared__ float s2[64];
        __shared__ float mag[16];
        int j = tid & 63, ch = tid >> 6;
        float acc = 0.0f;
        int r0 = ch * 256;
        #pragma unroll 8
        for (int r = 0; r < 256; r++)
            acc += g_v2[r0 + r] * __ldg(&fw3[(r0 + r) * 64 + j]);
        s[ch][j] = acc;
        asm volatile("bar.sync 1, 256;" ::: "memory");
        if (tid < 64) s2[tid] = s[0][tid] + s[1][tid] + s[2][tid] + s[3][tid] + fb3[tid];
        asm volatile("bar.sync 1, 256;" ::: "memory");
        if (tid < 16) {
            float a = s2[4 * tid], b = s2[4 * tid + 1],
                  c = s2[4 * tid + 2], d = s2[4 * tid + 3];
            mag[tid] = sqrtf(a * a + b * b + c * c + d * d);
        }
        asm volatile("bar.sync 1, 256;" ::: "memory");
        if (tid < 64) out[tid] = s2[tid] / mag[tid >> 2];
    }
}

// ---------------- launcher: three kernels -----------------------------------
extern "C" void kernel_launch(void* const* d_in, const int* in_sizes, int n_in,
                              void* d_out, int out_size) {
    const float* x   = (const float*)d_in[0];
    const int*   ei  = (const int*)  d_in[1];
    const float* w1  = (const float*)d_in[2];
    const float* b1  = (const float*)d_in[3];
    const float* w2  = (const float*)d_in[4];
    const float* b2  = (const float*)d_in[5];
    const float* qw1 = (const float*)d_in[6];
    const float* qb1 = (const float*)d_in[7];
    const float* qw2 = (const float*)d_in[8];
    const float* qb2 = (const float*)d_in[9];
    const float* qw3 = (const float*)d_in[10];
    const float* qb3 = (const float*)d_in[11];
    const float* fw1 = (const float*)d_in[12];
    const float* fb1 = (const float*)d_in[13];
    const float* fw2 = (const float*)d_in[14];
    const float* fb2 = (const float*)d_in[15];
    const float* fw3 = (const float*)d_in[16];
    const float* fb3 = (const float*)d_in[17];

    k_pre <<<GB_PRE, NTP>>>(x, ei, w1, b1, w2, b2,
                            qw1, qb1, qw2, qb2, qw3, qb3);
    k_fc1 <<<FC1_GRID, 256>>>(fw1);
    k_post<<<GB_POST, NT>>>(fb1, fw2, fb2, fw3, fb3, (float*)d_out);
}

// round 10
// speedup vs baseline: 1.8900x; 1.0011x over previous
#include <cuda_runtime.h>
#include <math.h>

#define Nn 1395
#define Ee 44640
#define MAXDEG 96        // >> max in-degree (Binomial mean 32, ~11 sigma headroom)
#define GB_PRE 140       // k_pre blocks (10 QConv nodes each; 140*10 >= 1395)
#define NTP 384
#define GSZP (GB_PRE * NTP)      // 53760 threads, 1680 warps
#define FC1_R 267840     // 1395 * 192
#define FC1_GRID 1184    // 148 SMs * 8 blocks, one wave at 100% occ
#define GB_POST 64
#define NT 512

// ---------------- scratch (device globals, allocation-free) ----------------
__device__ int   g_cnt[Nn];                 // in-degree (excl. self loop)
__device__ int   g_csc[Nn * MAXDEG];        // src lists per destination
__device__ __align__(16) float g_h0[Nn * 32];   // gcn1 transformed
__device__ __align__(16) float g_t2[Nn * 30];   // gcn2 transformed (pre-agg)
__device__ __align__(16) float g_h2[Nn * 30];   // gcn2 output (post leaky)
__device__ __align__(16) float g_v [Nn * 192];  // QConv output, flattened
__device__ __align__(16) float g_p1[FC1_GRID * 1024];
__device__ __align__(16) float g_v1[1024];
__device__ __align__(16) float g_p2[GB_POST * 1024];
__device__ __align__(16) float g_v2[1024];

// ---------------- software grid barrier ------------------------------------
__device__ int g_bar_count;
__device__ volatile int g_bar_gen;

__device__ __forceinline__ void gridbar(int nblocks) {
    __threadfence();
    __syncthreads();
    if (threadIdx.x == 0) {
        int gen = g_bar_gen;
        if (atomicAdd(&g_bar_count, 1) == nblocks - 1) {
            g_bar_count = 0;
            __threadfence();
            g_bar_gen = gen + 1;
        } else {
            while (g_bar_gen == gen) { }
        }
        __threadfence();
    }
    __syncthreads();
}

__device__ __forceinline__ float leaky(float v) { return v > 0.0f ? v : 0.2f * v; }

// ============================================================================
// Kernel 1: CSC build + GCN1 + GCN2 (gather) + fused QConv chain -> g_v
// ============================================================================
__global__ void __launch_bounds__(NTP)
k_pre(const float* __restrict__ x,   const int*   __restrict__ ei,
      const float* __restrict__ w1,  const float* __restrict__ b1,
      const float* __restrict__ w2,  const float* __restrict__ b2,
      const float* __restrict__ qw1, const float* __restrict__ qb1,
      const float* __restrict__ qw2, const float* __restrict__ qb2,
      const float* __restrict__ qw3, const float* __restrict__ qb3)
{
    const int tid  = threadIdx.x;
    const int bid  = blockIdx.x;
    const int gid  = bid * NTP + tid;
    const int wgid = gid >> 5;
    const int lane = gid & 31;

    // ---- P0: zero edge counters ----
    for (int i = gid; i < Nn; i += GSZP) g_cnt[i] = 0;
    gridbar(GB_PRE);

    // ---- P1: CSC fill (44640 atomics) + GCN1 transform (x[:, :3] == 0) ----
    for (int e = gid; e < Ee; e += GSZP) {
        int s = ei[e], d = ei[Ee + e];
        int pos = atomicAdd(&g_cnt[d], 1);
        if (pos < MAXDEG) g_csc[d * MAXDEG + pos] = s;
    }
    for (int i = gid; i < Nn * 32; i += GSZP) {
        int n = i >> 5, c = i & 31;
        g_h0[i] = x[n * 6 + 3] * w1[3 * 32 + c]
                + x[n * 6 + 4] * w1[4 * 32 + c]
                + x[n * 6 + 5] * w1[5 * 32 + c];
    }
    gridbar(GB_PRE);

    // ---- P2: GCN1 gather-aggregate + finalize + GCN2 transform (fused) ----
    // Warp per destination node; lane = channel (32).
    for (int d = wgid; d < Nn; d += GSZP / 32) {
        int cntd = g_cnt[d];
        float dinvd = rsqrtf((float)(cntd + 1));
        float acc = dinvd * dinvd * g_h0[d * 32 + lane];   // self loop
        const int* lst = g_csc + d * MAXDEG;
        #pragma unroll 4
        for (int j = 0; j < cntd; j++) {
            int s = lst[j];                                 // warp-uniform
            float coef = rsqrtf((float)(g_cnt[s] + 1)) * dinvd;
            acc += coef * g_h0[s * 32 + lane];
        }
        float h1 = leaky(acc + b1[lane]);
        // GCN2 transform: t2[d,c] = sum_k h1_k * w2[k,c]  (c = lane < 30)
        float t = 0.0f;
        #pragma unroll
        for (int k = 0; k < 32; k++) {
            float hk = __shfl_sync(0xffffffffu, h1, k);
            if (lane < 30) t += hk * __ldg(&w2[k * 30 + lane]);
        }
        if (lane < 30) g_t2[d * 30 + lane] = t;
    }
    gridbar(GB_PRE);

    // ---- P3: GCN2 gather-aggregate + finalize ----
    for (int d = wgid; d < Nn; d += GSZP / 32) {
        int cntd = g_cnt[d];
        float dinvd = rsqrtf((float)(cntd + 1));
        float acc = (lane < 30) ? dinvd * dinvd * g_t2[d * 30 + lane] : 0.0f;
        const int* lst = g_csc + d * MAXDEG;
        #pragma unroll 4
        for (int j = 0; j < cntd; j++) {
            int s = lst[j];
            float coef = rsqrtf((float)(g_cnt[s] + 1)) * dinvd;
            if (lane < 30) acc += coef * g_t2[s * 30 + lane];
        }
        if (lane < 30) g_h2[d * 30 + lane] = leaky(acc + b2[lane]);
    }
    gridbar(GB_PRE);

    // ---- P4: fused QConv chain 30->192->192->192, 10 nodes per block ----
    {
        __shared__ float s_in[10][30];
        __shared__ float sa[10][192];
        __shared__ float sb[10][192];
        const int half = tid / 192;          // 0 or 1
        const int c    = tid - half * 192;   // 0..191
        const int nb   = bid * 10;

        for (int i = tid; i < 10 * 30; i += NTP) {
            int node = nb + i / 30;
            if (node < Nn) s_in[i / 30][i % 30] = g_h2[node * 30 + (i % 30)];
        }
        __syncthreads();

        float acc[5];
        #pragma unroll
        for (int g = 0; g < 5; g++) acc[g] = qb1[c];
        #pragma unroll
        for (int k = 0; k < 30; k++) {
            float w = __ldg(&qw1[k * 192 + c]);
            #pragma unroll
            for (int g = 0; g < 5; g++) acc[g] += s_in[half * 5 + g][k] * w;
        }
        #pragma unroll
        for (int g = 0; g < 5; g++) sa[half * 5 + g][c] = acc[g];
        __syncthreads();

        #pragma unroll
        for (int g = 0; g < 5; g++) acc[g] = qb2[c];
        #pragma unroll 8
        for (int k = 0; k < 192; k++) {
            float w = __ldg(&qw2[k * 192 + c]);
            #pragma unroll
            for (int g = 0; g < 5; g++) acc[g] += sa[half * 5 + g][k] * w;
        }
        #pragma unroll
        for (int g = 0; g < 5; g++) sb[half * 5 + g][c] = acc[g];
        __syncthreads();

        #pragma unroll
        for (int g = 0; g < 5; g++) acc[g] = qb3[c];
        #pragma unroll 8
        for (int k = 0; k < 192; k++) {
            float w = __ldg(&qw3[k * 192 + c]);
            #pragma unroll
            for (int g = 0; g < 5; g++) acc[g] += sb[half * 5 + g][k] * w;
        }
        #pragma unroll
        for (int g = 0; g < 5; g++) {
            int node = nb + half * 5 + g;
            if (node < Nn) g_v[node * 192 + c] = acc[g];
        }
    }
}

// ============================================================================
// Kernel 2: fc1 partials — lean streaming kernel, 100% occupancy, one wave.
// ============================================================================
__global__ void __launch_bounds__(256, 8)
k_fc1(const float* __restrict__ fw1)
{
    const float4* W = (const float4*)fw1 + (size_t)blockIdx.x * 256 + threadIdx.x;
    const float*  V = g_v + blockIdx.x;
    const int n = (FC1_R - blockIdx.x + FC1_GRID - 1) / FC1_GRID;
    float4 acc = make_float4(0.f, 0.f, 0.f, 0.f);
    #pragma unroll 4
    for (int it = 0; it < n; it++) {
        float  vv = __ldg(V);
        float4 w  = __ldcs(W);
        V += FC1_GRID;
        W += (size_t)FC1_GRID * 256;
        acc.x += vv * w.x; acc.y += vv * w.y;
        acc.z += vv * w.z; acc.w += vv * w.w;
    }
    ((float4*)(g_p1 + (size_t)blockIdx.x * 1024))[threadIdx.x] = acc;
}

// ============================================================================
// Kernel 3: fc1 reduce -> fc2 -> fc2 reduce -> fc3 + quaternion normalize
// ============================================================================
__global__ void __launch_bounds__(NT, 2)
k_post(const float* __restrict__ fb1,
       const float* __restrict__ fw2, const float* __restrict__ fb2,
       const float* __restrict__ fw3, const float* __restrict__ fb3,
       float* __restrict__ out)
{
    const int tid = threadIdx.x;
    const int bid = blockIdx.x;
    const int wid  = tid >> 5;
    const int lane = tid & 31;

    // ---- A: v1[j] = sum_b p1[b][j] + fb1[j]; warp-per-output ----
    {
        int j = bid * 16 + wid;
        float s = 0.0f;
        #pragma unroll 4
        for (int b = lane; b < FC1_GRID; b += 32)
            s += g_p1[(size_t)b * 1024 + j];
        #pragma unroll
        for (int o = 16; o > 0; o >>= 1)
            s += __shfl_down_sync(0xffffffffu, s, o);
        if (lane == 0) g_v1[j] = s + fb1[j];
    }
    gridbar(GB_POST);

    // ---- B: fc2 partials: block b covers rows [b*16, b*16+16) ----
    {
        __shared__ float4 sh[256];
        int half = tid >> 8, lt = tid & 255;
        int r0 = bid * 16 + half * 8;
        const float4* W = (const float4*)fw2 + (size_t)r0 * 256 + lt;
        float4 acc = make_float4(0.f, 0.f, 0.f, 0.f);
        #pragma unroll
        for (int r = 0; r < 8; r++) {
            float vv = g_v1[r0 + r];
            float4 w = __ldg(W);
            W += 256;
            acc.x += vv * w.x; acc.y += vv * w.y;
            acc.z += vv * w.z; acc.w += vv * w.w;
        }
        if (half == 1) sh[lt] = acc;
        __syncthreads();
        if (half == 0) {
            float4 o = sh[lt];
            acc.x += o.x; acc.y += o.y; acc.z += o.z; acc.w += o.w;
            ((float4*)(g_p2 + (size_t)bid * 1024))[lt] = acc;
        }
    }
    gridbar(GB_POST);

    // ---- C: v2[j] = sum_b p2[b][j] + fb2[j]; warp-per-output ----
    {
        int j = bid * 16 + wid;
        float s = g_p2[(size_t)lane * 1024 + j]
                + g_p2[(size_t)(lane + 32) * 1024 + j];
        #pragma unroll
        for (int o = 16; o > 0; o >>= 1)
            s += __shfl_down_sync(0xffffffffu, s, o);
        if (lane == 0) g_v2[j] = s + fb2[j];
    }
    gridbar(GB_POST);

    // ---- D: fc3 (1024->64) + quaternion group-of-4 normalize (block 0) ----
    if (bid == 0 && tid < 256) {
        __shared__ float s[4][64];
        __shared__ float s2[64];
        __shared__ float mag[16];
        int j = tid & 63, ch = tid >> 6;
        float acc = 0.0f;
        int r0 = ch * 256;
        #pragma unroll 8
        for (int r = 0; r < 256; r++)
            acc += g_v2[r0 + r] * __ldg(&fw3[(r0 + r) * 64 + j]);
        s[ch][j] = acc;
        asm volatile("bar.sync 1, 256;" ::: "memory");
        if (tid < 64) s2[tid] = s[0][tid] + s[1][tid] + s[2][tid] + s[3][tid] + fb3[tid];
        asm volatile("bar.sync 1, 256;" ::: "memory");
        if (tid < 16) {
            float a = s2[4 * tid], b = s2[4 * tid + 1],
                  c = s2[4 * tid + 2], d = s2[4 * tid + 3];
            mag[tid] = sqrtf(a * a + b * b + c * c + d * d);
        }
        asm volatile("bar.sync 1, 256;" ::: "memory");
        if (tid < 64) out[tid] = s2[tid] / mag[tid >> 2];
    }
}

// ---------------- launcher: three kernels -----------------------------------
extern "C" void kernel_launch(void* const* d_in, const int* in_sizes, int n_in,
                              void* d_out, int out_size) {
    const float* x   = (const float*)d_in[0];
    const int*   ei  = (const int*)  d_in[1];
    const float* w1  = (const float*)d_in[2];
    const float* b1  = (const float*)d_in[3];
    const float* w2  = (const float*)d_in[4];
    const float* b2  = (const float*)d_in[5];
    const float* qw1 = (const float*)d_in[6];
    const float* qb1 = (const float*)d_in[7];
    const float* qw2 = (const float*)d_in[8];
    const float* qb2 = (const float*)d_in[9];
    const float* qw3 = (const float*)d_in[10];
    const float* qb3 = (const float*)d_in[11];
    const float* fw1 = (const float*)d_in[12];
    const float* fb1 = (const float*)d_in[13];
    const float* fw2 = (const float*)d_in[14];
    const float* fb2 = (const float*)d_in[15];
    const float* fw3 = (const float*)d_in[16];
    const float* fb3 = (const float*)d_in[17];

    k_pre <<<GB_PRE, NTP>>>(x, ei, w1, b1, w2, b2,
                            qw1, qb1, qw2, qb2, qw3, qb3);
    k_fc1 <<<FC1_GRID, 256>>>(fw1);
    k_post<<<GB_POST, NT>>>(fb1, fw2, fb2, fw3, fb3, (float*)d_out);
}